// round 14
// baseline (speedup 1.0000x reference)
#include <cuda_runtime.h>
#include <cuda_fp16.h>
#include <stdint.h>

// ---------------- problem constants ----------------
static constexpr int MROWS = 8192;          // 16*512
static constexpr int FLAT  = 12544;         // 7*7*256
static constexpr int HID   = 1024;
static constexpr int NCLS  = 81;
static constexpr int NPAD  = 128;

// prep kernel block ranges
static constexpr int T1 = (HID / 32) * (FLAT / 32);   // 12544 W1 tiles
static constexpr int T2 = (HID / 32) * (HID / 32);    // 1024  W2 tiles
static constexpr int T3 = (NPAD / 32) * (HID / 32);   // 128   W3 tiles

// ---------------- scratch (__device__ globals; no allocs allowed) ----------
__device__ __half g_featH[(size_t)MROWS * FLAT];   // compacted fp16 A
__device__ __half g_W1t[(size_t)HID * FLAT];       // [N,K] K-major
__device__ __half g_W2t[(size_t)HID * HID];
__device__ __half g_W3t[(size_t)NPAD * HID];       // rows 81..127 zero
__device__ __half g_H1[(size_t)MROWS * HID];
__device__ __half g_H2[(size_t)MROWS * HID];
__device__ int    g_idx[MROWS];
__device__ int    g_cnt;

// ---------------- helpers ----------------
__device__ __forceinline__ uint32_t smem_u32(const void* p) {
    uint32_t a;
    asm("{ .reg .u64 t; cvta.to.shared.u64 t, %1; cvt.u32.u64 %0, t; }" : "=r"(a) : "l"(p));
    return a;
}
#define SWZ(o) ((o) ^ (((o) >> 3) & 0x70))

__device__ __forceinline__ void cp16(uint32_t dst, const void* src) {
    asm volatile("cp.async.cg.shared.global [%0], [%1], 16;" :: "r"(dst), "l"(src) : "memory");
}
__device__ __forceinline__ void cp_commit() { asm volatile("cp.async.commit_group;" ::: "memory"); }
__device__ __forceinline__ void cp_wait1() { asm volatile("cp.async.wait_group 1;" ::: "memory"); }
__device__ __forceinline__ void cp_wait0() { asm volatile("cp.async.wait_group 0;" ::: "memory"); }

__device__ __forceinline__ void ldsm4(uint32_t (&r)[4], uint32_t addr) {
    asm volatile("ldmatrix.sync.aligned.m8n8.x4.shared.b16 {%0,%1,%2,%3}, [%4];"
        : "=r"(r[0]), "=r"(r[1]), "=r"(r[2]), "=r"(r[3]) : "r"(addr));
}
__device__ __forceinline__ void mma16816(float (&d)[4], const uint32_t (&a)[4],
                                         uint32_t b0, uint32_t b1) {
    asm volatile("mma.sync.aligned.m16n8k16.row.col.f32.f16.f16.f32 "
        "{%0,%1,%2,%3}, {%4,%5,%6,%7}, {%8,%9}, {%0,%1,%2,%3};"
        : "+f"(d[0]), "+f"(d[1]), "+f"(d[2]), "+f"(d[3])
        : "r"(a[0]), "r"(a[1]), "r"(a[2]), "r"(a[3]), "r"(b0), "r"(b1));
}

// ---------------- valid-row compaction (ballot scan, stable) ----------------
__global__ void build_idx(const void* __restrict__ maskp,
                          int* __restrict__ idx, int* __restrict__ cntp) {
    __shared__ int swarp[32];
    __shared__ int s_is8, s_base, s_total;
    const int tid = threadIdx.x, wid = tid >> 5, lane = tid & 31;
    if (tid == 0) {
        const unsigned char* m8 = (const unsigned char*)maskp;
        bool i8 = false;
        for (int i = 1; i < 256; ++i)
            if ((i & 3) && m8[i]) i8 = true;
        s_is8 = i8 ? 1 : 0;
        s_base = 0;
    }
    __syncthreads();
    const int is8 = s_is8;
    for (int chunk = 0; chunk < MROWS; chunk += 1024) {
        const int r = chunk + tid;
        const int v = is8 ? (((const unsigned char*)maskp)[r] != 0)
                          : (((const int*)maskp)[r] != 0);
        const unsigned bal = __ballot_sync(0xFFFFFFFFu, v);
        const int lanePre = __popc(bal & ((1u << lane) - 1u));
        if (lane == 0) swarp[wid] = __popc(bal);
        __syncthreads();
        if (wid == 0) {
            int orig = swarp[lane], x = orig;
            #pragma unroll
            for (int off = 1; off < 32; off <<= 1) {
                int y = __shfl_up_sync(0xFFFFFFFFu, x, off);
                if (lane >= off) x += y;
            }
            swarp[lane] = x - orig;           // exclusive prefix
            if (lane == 31) s_total = x;
        }
        __syncthreads();
        if (v) idx[s_base + swarp[wid] + lanePre] = r;
        __syncthreads();
        if (tid == 0) s_base += s_total;
        __syncthreads();
    }
    if (tid == 0) *cntp = s_base;
}

// ---------------- fused prep: row gather+cvt AND all weight transposes -----
__global__ void __launch_bounds__(256)
prep(const float* __restrict__ feat, const int* __restrict__ idx,
     const int* __restrict__ cntp, __half* __restrict__ fOut,
     const float* __restrict__ W1, const float* __restrict__ W2,
     const float* __restrict__ W3, __half* __restrict__ W1t,
     __half* __restrict__ W2t, __half* __restrict__ W3t) {
    __shared__ float t[32][33];
    int b = blockIdx.x;
    const int tid = threadIdx.x;

    if (b < MROWS) {                              // ---- gather role ----
        if (b >= *cntp) return;
        const float4* in = (const float4*)(feat + (size_t)idx[b] * FLAT);
        uint2* o = (uint2*)(fOut + (size_t)b * FLAT);
        for (int i = tid; i < FLAT / 4; i += 256) {
            float4 v = in[i];
            __half2 a = __floats2half2_rn(v.x, v.y), bb = __floats2half2_rn(v.z, v.w);
            o[i] = make_uint2(*(uint32_t*)&a, *(uint32_t*)&bb);
        }
        return;
    }
    b -= MROWS;                                   // ---- transpose role ----
    const float* W; __half* Wt; int K, N, nx;
    if (b < T1)      { W = W1; Wt = W1t; K = FLAT; N = HID;  nx = HID / 32; }
    else if (b < T1 + T2) { b -= T1; W = W2; Wt = W2t; K = HID; N = HID; nx = HID / 32; }
    else             { b -= T1 + T2; W = W3; Wt = W3t; K = HID; N = NCLS; nx = NPAD / 32; }
    const int n0 = (b % nx) * 32, k0 = (b / nx) * 32;
    const int tx = tid & 31, ty = tid >> 5;
    #pragma unroll
    for (int i = 0; i < 32; i += 8) {
        int n = n0 + tx;
        t[ty + i][tx] = (n < N) ? W[(size_t)(k0 + ty + i) * N + n] : 0.f;
    }
    __syncthreads();
    #pragma unroll
    for (int i = 0; i < 32; i += 8)
        Wt[(size_t)(n0 + ty + i) * K + k0 + tx] = __float2half_rn(t[tx][ty + i]);
}

// ---------------- HMMA GEMM: C = post(A[Mc,K] @ Wt[N,K]^T + bias) ----------
// BM=64, BN=64, BK=64. 128 thr = 4 warps (2Mx2N), warp tile 32x32, acc=32.
// 2-stage cp.async (32 KB) -> 6 CTAs/SM (24 warps): occupancy over pipeline depth.
// Compacted rows; CTAs beyond padded count early-exit.
// MODE 0: relu, fp16 out (stride HID).  MODE 1: scatter via idx, fp32 out (stride NCLS).
template <int MODE>
__global__ void __launch_bounds__(128, 6)
gemm_hmma(const __half* __restrict__ A, const __half* __restrict__ Wt,
          const float* __restrict__ bias, void* __restrict__ outp,
          const int* __restrict__ idx, const int* __restrict__ cntp, int K) {
    constexpr int A_BYTES = 64 * 128;
    constexpr int B_BYTES = 64 * 128;
    constexpr int STAGE   = A_BYTES + B_BYTES;   // 16 KB

    const int cnt = *cntp;
    const int m0 = blockIdx.y * 64;
    if (m0 >= ((cnt + 63) & ~63)) return;

    extern __shared__ char smem[];
    const uint32_t tiles = smem_u32(smem);

    const int tid = threadIdx.x, wid = tid >> 5, lid = tid & 31;
    const int n0 = blockIdx.x * 64;
    const int wm = (wid >> 1) * 32, wn = (wid & 1) * 32;
    const int KC = K >> 6;

    float acc[2][4][4];
    #pragma unroll
    for (int a = 0; a < 2; ++a)
        #pragma unroll
        for (int b = 0; b < 4; ++b)
            #pragma unroll
            for (int c = 0; c < 4; ++c) acc[a][b][c] = 0.f;

    auto load_stage = [&](int c) {
        const uint32_t sA = tiles + (uint32_t)(c & 1) * STAGE, sB = sA + A_BYTES;
        const __half* Ab = A + (size_t)m0 * K + (c << 6);
        const __half* Bb = Wt + (size_t)n0 * K + (c << 6);
        #pragma unroll
        for (int i = 0; i < 4; ++i) {
            int op = tid + i * 128, row = op >> 3, seg = op & 7;
            cp16(sA + SWZ((uint32_t)(row * 128 + seg * 16)), Ab + (size_t)row * K + seg * 8);
        }
        #pragma unroll
        for (int i = 0; i < 4; ++i) {
            int op = tid + i * 128, row = op >> 3, seg = op & 7;
            cp16(sB + SWZ((uint32_t)(row * 128 + seg * 16)), Bb + (size_t)row * K + seg * 8);
        }
        cp_commit();
    };

    load_stage(0);
    if (KC > 1) load_stage(1);

    const int lrow = lid & 15, lkh = lid >> 4;
    for (int c = 0; c < KC; ++c) {
        if (c >= KC - 1) cp_wait0(); else cp_wait1();
        __syncthreads();
        const uint32_t sA = tiles + (uint32_t)(c & 1) * STAGE, sB = sA + A_BYTES;
        #pragma unroll
        for (int k0 = 0; k0 < 64; k0 += 16) {
            uint32_t bfr[2][4];
            #pragma unroll
            for (int nn = 0; nn < 2; ++nn) {
                uint32_t off = (uint32_t)((wn + nn * 16 + lrow) * 128 + (k0 + lkh * 8) * 2);
                ldsm4(bfr[nn], sB + SWZ(off));
            }
            #pragma unroll
            for (int ms = 0; ms < 2; ++ms) {
                uint32_t afr[4];
                uint32_t off = (uint32_t)((wm + ms * 16 + lrow) * 128 + (k0 + lkh * 8) * 2);
                ldsm4(afr, sA + SWZ(off));
                #pragma unroll
                for (int ns = 0; ns < 4; ++ns)
                    mma16816(acc[ms][ns], afr, bfr[ns >> 1][ns & 1], bfr[ns >> 1][(ns & 1) + 2]);
            }
        }
        __syncthreads();
        if (c + 2 < KC) load_stage(c + 2);   // stage (c&1) now free
    }

    #pragma unroll
    for (int ms = 0; ms < 2; ++ms) {
        const int r0 = m0 + wm + ms * 16 + (lid >> 2);
        #pragma unroll
        for (int ns = 0; ns < 4; ++ns) {
            const int col = n0 + wn + ns * 8 + 2 * (lid & 3);
            if (MODE == 0) {
                float bx = bias[col], by = bias[col + 1];
                __half* o = (__half*)outp;
                *(__half2*)(o + (size_t)r0 * HID + col) =
                    __floats2half2_rn(fmaxf(acc[ms][ns][0] + bx, 0.f),
                                      fmaxf(acc[ms][ns][1] + by, 0.f));
                *(__half2*)(o + (size_t)(r0 + 8) * HID + col) =
                    __floats2half2_rn(fmaxf(acc[ms][ns][2] + bx, 0.f),
                                      fmaxf(acc[ms][ns][3] + by, 0.f));
            } else {
                float* o = (float*)outp;
                #pragma unroll
                for (int h = 0; h < 2; ++h) {
                    const int rr = r0 + h * 8;
                    if (rr < cnt) {
                        const int orow = idx[rr];
                        if (col < NCLS)
                            o[(size_t)orow * NCLS + col] = acc[ms][ns][2 * h] + bias[col];
                        if (col + 1 < NCLS)
                            o[(size_t)orow * NCLS + col + 1] = acc[ms][ns][2 * h + 1] + bias[col + 1];
                    }
                }
            }
        }
    }
}

// ---------------- launcher ----------------
extern "C" void kernel_launch(void* const* d_in, const int* in_sizes, int n_in,
                              void* d_out, int out_size) {
    const float* feat = (const float*)d_in[0];
    const void*  mask = d_in[1];
    const float* W1 = (const float*)d_in[2]; const float* b1 = (const float*)d_in[3];
    const float* W2 = (const float*)d_in[4]; const float* b2 = (const float*)d_in[5];
    const float* W3 = (const float*)d_in[6]; const float* b3 = (const float*)d_in[7];

    void *pF, *pW1, *pW2, *pW3, *pH1, *pH2, *pIdx, *pCnt;
    cudaGetSymbolAddress(&pF,  g_featH);
    cudaGetSymbolAddress(&pW1, g_W1t);
    cudaGetSymbolAddress(&pW2, g_W2t);
    cudaGetSymbolAddress(&pW3, g_W3t);
    cudaGetSymbolAddress(&pH1, g_H1);
    cudaGetSymbolAddress(&pH2, g_H2);
    cudaGetSymbolAddress(&pIdx, g_idx);
    cudaGetSymbolAddress(&pCnt, g_cnt);

    constexpr int SMEM = 2 * (64 * 128 + 64 * 128);   // 32 KB
    cudaFuncSetAttribute(gemm_hmma<0>, cudaFuncAttributeMaxDynamicSharedMemorySize, SMEM);
    cudaFuncSetAttribute(gemm_hmma<1>, cudaFuncAttributeMaxDynamicSharedMemorySize, SMEM);

    // output zeros (invalid rows stay 0)
    cudaMemsetAsync(d_out, 0, (size_t)out_size * sizeof(float));
    // valid-row compaction
    build_idx<<<1, 1024>>>(mask, (int*)pIdx, (int*)pCnt);
    // fused prep: gather+convert valid rows AND all 3 weight transposes
    prep<<<MROWS + T1 + T2 + T3, 256>>>(
        feat, (const int*)pIdx, (const int*)pCnt, (__half*)pF,
        W1, W2, W3, (__half*)pW1, (__half*)pW2, (__half*)pW3);
    // MLP on compacted rows (grid.x = N-tiles so concurrent CTAs share A via L2)
    gemm_hmma<0><<<dim3(HID / 64, MROWS / 64), 128, SMEM>>>(
        (const __half*)pF, (const __half*)pW1, b1, pH1,
        (const int*)pIdx, (const int*)pCnt, FLAT);
    gemm_hmma<0><<<dim3(HID / 64, MROWS / 64), 128, SMEM>>>(
        (const __half*)pH1, (const __half*)pW2, b2, pH2,
        (const int*)pIdx, (const int*)pCnt, HID);
    gemm_hmma<1><<<dim3(NPAD / 64, MROWS / 64), 128, SMEM>>>(
        (const __half*)pH2, (const __half*)pW3, b3, d_out,
        (const int*)pIdx, (const int*)pCnt, HID);
    (void)in_sizes; (void)n_in;
}

// round 15
// speedup vs baseline: 1.0339x; 1.0339x over previous
#include <cuda_runtime.h>
#include <cuda_fp16.h>
#include <stdint.h>

// ---------------- problem constants ----------------
static constexpr int MROWS = 8192;          // 16*512
static constexpr int FLAT  = 12544;         // 7*7*256
static constexpr int HID   = 1024;
static constexpr int NCLS  = 81;
static constexpr int NPAD  = 128;

// prep kernel block ranges
static constexpr int T1 = (HID / 32) * (FLAT / 32);   // 12544 W1 tiles
static constexpr int T2 = (HID / 32) * (HID / 32);    // 1024  W2 tiles
static constexpr int T3 = (NPAD / 32) * (HID / 32);   // 128   W3 tiles

// ---------------- scratch (__device__ globals; no allocs allowed) ----------
__device__ __half g_featH[(size_t)MROWS * FLAT];   // compacted fp16 A
__device__ __half g_W1t[(size_t)HID * FLAT];       // [N,K] K-major
__device__ __half g_W2t[(size_t)HID * HID];
__device__ __half g_W3t[(size_t)NPAD * HID];       // rows 81..127 zero
__device__ __half g_H1[(size_t)MROWS * HID];
__device__ __half g_H2[(size_t)MROWS * HID];
__device__ int    g_idx[MROWS];
__device__ int    g_cnt;

// ---------------- helpers ----------------
__device__ __forceinline__ uint32_t smem_u32(const void* p) {
    uint32_t a;
    asm("{ .reg .u64 t; cvta.to.shared.u64 t, %1; cvt.u32.u64 %0, t; }" : "=r"(a) : "l"(p));
    return a;
}
#define SWZ(o) ((o) ^ (((o) >> 3) & 0x70))

__device__ __forceinline__ void cp16(uint32_t dst, const void* src) {
    asm volatile("cp.async.cg.shared.global [%0], [%1], 16;" :: "r"(dst), "l"(src) : "memory");
}
__device__ __forceinline__ void cp_commit() { asm volatile("cp.async.commit_group;" ::: "memory"); }
__device__ __forceinline__ void cp_wait1() { asm volatile("cp.async.wait_group 1;" ::: "memory"); }
__device__ __forceinline__ void cp_wait0() { asm volatile("cp.async.wait_group 0;" ::: "memory"); }

__device__ __forceinline__ void ldsm4(uint32_t (&r)[4], uint32_t addr) {
    asm volatile("ldmatrix.sync.aligned.m8n8.x4.shared.b16 {%0,%1,%2,%3}, [%4];"
        : "=r"(r[0]), "=r"(r[1]), "=r"(r[2]), "=r"(r[3]) : "r"(addr));
}
__device__ __forceinline__ void mma16816(float (&d)[4], const uint32_t (&a)[4],
                                         uint32_t b0, uint32_t b1) {
    asm volatile("mma.sync.aligned.m16n8k16.row.col.f32.f16.f16.f32 "
        "{%0,%1,%2,%3}, {%4,%5,%6,%7}, {%8,%9}, {%0,%1,%2,%3};"
        : "+f"(d[0]), "+f"(d[1]), "+f"(d[2]), "+f"(d[3])
        : "r"(a[0]), "r"(a[1]), "r"(a[2]), "r"(a[3]), "r"(b0), "r"(b1));
}

// ---------------- valid-row compaction (ballot scan, stable) ----------------
__global__ void build_idx(const void* __restrict__ maskp,
                          int* __restrict__ idx, int* __restrict__ cntp) {
    __shared__ int swarp[32];
    __shared__ int s_is8, s_base, s_total;
    const int tid = threadIdx.x, wid = tid >> 5, lane = tid & 31;
    if (tid == 0) {
        const unsigned char* m8 = (const unsigned char*)maskp;
        bool i8 = false;
        for (int i = 1; i < 256; ++i)
            if ((i & 3) && m8[i]) i8 = true;
        s_is8 = i8 ? 1 : 0;
        s_base = 0;
    }
    __syncthreads();
    const int is8 = s_is8;
    for (int chunk = 0; chunk < MROWS; chunk += 1024) {
        const int r = chunk + tid;
        const int v = is8 ? (((const unsigned char*)maskp)[r] != 0)
                          : (((const int*)maskp)[r] != 0);
        const unsigned bal = __ballot_sync(0xFFFFFFFFu, v);
        const int lanePre = __popc(bal & ((1u << lane) - 1u));
        if (lane == 0) swarp[wid] = __popc(bal);
        __syncthreads();
        if (wid == 0) {
            int orig = swarp[lane], x = orig;
            #pragma unroll
            for (int off = 1; off < 32; off <<= 1) {
                int y = __shfl_up_sync(0xFFFFFFFFu, x, off);
                if (lane >= off) x += y;
            }
            swarp[lane] = x - orig;           // exclusive prefix
            if (lane == 31) s_total = x;
        }
        __syncthreads();
        if (v) idx[s_base + swarp[wid] + lanePre] = r;
        __syncthreads();
        if (tid == 0) s_base += s_total;
        __syncthreads();
    }
    if (tid == 0) *cntp = s_base;
}

// ---------------- fused prep: row gather+cvt AND all weight transposes -----
__global__ void __launch_bounds__(256)
prep(const float* __restrict__ feat, const int* __restrict__ idx,
     const int* __restrict__ cntp, __half* __restrict__ fOut,
     const float* __restrict__ W1, const float* __restrict__ W2,
     const float* __restrict__ W3, __half* __restrict__ W1t,
     __half* __restrict__ W2t, __half* __restrict__ W3t) {
    __shared__ float t[32][33];
    int b = blockIdx.x;
    const int tid = threadIdx.x;

    if (b < MROWS) {                              // ---- gather role ----
        if (b >= *cntp) return;
        const float4* in = (const float4*)(feat + (size_t)idx[b] * FLAT);
        uint2* o = (uint2*)(fOut + (size_t)b * FLAT);
        for (int i = tid; i < FLAT / 4; i += 256) {
            float4 v = in[i];
            __half2 a = __floats2half2_rn(v.x, v.y), bb = __floats2half2_rn(v.z, v.w);
            o[i] = make_uint2(*(uint32_t*)&a, *(uint32_t*)&bb);
        }
        return;
    }
    b -= MROWS;                                   // ---- transpose role ----
    const float* W; __half* Wt; int K, N, nx;
    if (b < T1)      { W = W1; Wt = W1t; K = FLAT; N = HID;  nx = HID / 32; }
    else if (b < T1 + T2) { b -= T1; W = W2; Wt = W2t; K = HID; N = HID; nx = HID / 32; }
    else             { b -= T1 + T2; W = W3; Wt = W3t; K = HID; N = NCLS; nx = NPAD / 32; }
    const int n0 = (b % nx) * 32, k0 = (b / nx) * 32;
    const int tx = tid & 31, ty = tid >> 5;
    #pragma unroll
    for (int i = 0; i < 32; i += 8) {
        int n = n0 + tx;
        t[ty + i][tx] = (n < N) ? W[(size_t)(k0 + ty + i) * N + n] : 0.f;
    }
    __syncthreads();
    #pragma unroll
    for (int i = 0; i < 32; i += 8)
        Wt[(size_t)(n0 + ty + i) * K + k0 + tx] = __float2half_rn(t[tx][ty + i]);
}

// ---------------- HMMA GEMM: C = post(A[Mc,K] @ Wt[N,K]^T + bias) ----------
// BM=64, BN=64, BK=64. 128 thr = 4 warps (2Mx2N), warp tile 32x32, acc=32.
// 3-stage cp.async (48 KB) -> 4 CTAs/SM. Fragment double-buffering at k0
// granularity: ldsm for k0+1 issues before the 8 mma of k0 consume their frags.
// Compacted rows; CTAs beyond padded count early-exit.
// MODE 0: relu, fp16 out (stride HID).  MODE 1: scatter via idx, fp32 out (stride NCLS).
template <int MODE>
__global__ void __launch_bounds__(128, 4)
gemm_hmma(const __half* __restrict__ A, const __half* __restrict__ Wt,
          const float* __restrict__ bias, void* __restrict__ outp,
          const int* __restrict__ idx, const int* __restrict__ cntp, int K) {
    constexpr int A_BYTES = 64 * 128;
    constexpr int B_BYTES = 64 * 128;
    constexpr int STAGE   = A_BYTES + B_BYTES;   // 16 KB

    const int cnt = *cntp;
    const int m0 = blockIdx.y * 64;
    if (m0 >= ((cnt + 63) & ~63)) return;

    extern __shared__ char smem[];
    const uint32_t tiles = smem_u32(smem);

    const int tid = threadIdx.x, wid = tid >> 5, lid = tid & 31;
    const int n0 = blockIdx.x * 64;
    const int wm = (wid >> 1) * 32, wn = (wid & 1) * 32;
    const int KC = K >> 6;

    float acc[2][4][4];
    #pragma unroll
    for (int a = 0; a < 2; ++a)
        #pragma unroll
        for (int b = 0; b < 4; ++b)
            #pragma unroll
            for (int c = 0; c < 4; ++c) acc[a][b][c] = 0.f;

    auto load_stage = [&](int c) {
        const uint32_t sA = tiles + (uint32_t)(c % 3) * STAGE, sB = sA + A_BYTES;
        const __half* Ab = A + (size_t)m0 * K + (c << 6);
        const __half* Bb = Wt + (size_t)n0 * K + (c << 6);
        #pragma unroll
        for (int i = 0; i < 4; ++i) {
            int op = tid + i * 128, row = op >> 3, seg = op & 7;
            cp16(sA + SWZ((uint32_t)(row * 128 + seg * 16)), Ab + (size_t)row * K + seg * 8);
        }
        #pragma unroll
        for (int i = 0; i < 4; ++i) {
            int op = tid + i * 128, row = op >> 3, seg = op & 7;
            cp16(sB + SWZ((uint32_t)(row * 128 + seg * 16)), Bb + (size_t)row * K + seg * 8);
        }
        cp_commit();
    };

    load_stage(0);
    load_stage(1);

    const int lrow = lid & 15, lkh = lid >> 4;
    uint32_t bfr[2][2][4], afr[2][2][4];
    for (int c = 0; c < KC; ++c) {
        if (c >= KC - 1) cp_wait0(); else cp_wait1();
        __syncthreads();
        if (c + 2 < KC) load_stage(c + 2);
        const uint32_t sA = tiles + (uint32_t)(c % 3) * STAGE, sB = sA + A_BYTES;

        // prologue: fragments for k0 = 0
        #pragma unroll
        for (int nn = 0; nn < 2; ++nn) {
            uint32_t off = (uint32_t)((wn + nn * 16 + lrow) * 128 + (lkh * 8) * 2);
            ldsm4(bfr[0][nn], sB + SWZ(off));
        }
        #pragma unroll
        for (int ms = 0; ms < 2; ++ms) {
            uint32_t off = (uint32_t)((wm + ms * 16 + lrow) * 128 + (lkh * 8) * 2);
            ldsm4(afr[0][ms], sA + SWZ(off));
        }
        #pragma unroll
        for (int k0i = 0; k0i < 4; ++k0i) {
            if (k0i < 3) {                         // prefetch k0+1 frags
                const int nk = (k0i + 1) * 16;
                #pragma unroll
                for (int nn = 0; nn < 2; ++nn) {
                    uint32_t off = (uint32_t)((wn + nn * 16 + lrow) * 128 + (nk + lkh * 8) * 2);
                    ldsm4(bfr[(k0i + 1) & 1][nn], sB + SWZ(off));
                }
                #pragma unroll
                for (int ms = 0; ms < 2; ++ms) {
                    uint32_t off = (uint32_t)((wm + ms * 16 + lrow) * 128 + (nk + lkh * 8) * 2);
                    ldsm4(afr[(k0i + 1) & 1][ms], sA + SWZ(off));
                }
            }
            const int bb = k0i & 1;
            #pragma unroll
            for (int ms = 0; ms < 2; ++ms)
                #pragma unroll
                for (int ns = 0; ns < 4; ++ns)
                    mma16816(acc[ms][ns], afr[bb][ms],
                             bfr[bb][ns >> 1][ns & 1], bfr[bb][ns >> 1][(ns & 1) + 2]);
        }
    }

    #pragma unroll
    for (int ms = 0; ms < 2; ++ms) {
        const int r0 = m0 + wm + ms * 16 + (lid >> 2);
        #pragma unroll
        for (int ns = 0; ns < 4; ++ns) {
            const int col = n0 + wn + ns * 8 + 2 * (lid & 3);
            if (MODE == 0) {
                float bx = bias[col], by = bias[col + 1];
                __half* o = (__half*)outp;
                *(__half2*)(o + (size_t)r0 * HID + col) =
                    __floats2half2_rn(fmaxf(acc[ms][ns][0] + bx, 0.f),
                                      fmaxf(acc[ms][ns][1] + by, 0.f));
                *(__half2*)(o + (size_t)(r0 + 8) * HID + col) =
                    __floats2half2_rn(fmaxf(acc[ms][ns][2] + bx, 0.f),
                                      fmaxf(acc[ms][ns][3] + by, 0.f));
            } else {
                float* o = (float*)outp;
                #pragma unroll
                for (int h = 0; h < 2; ++h) {
                    const int rr = r0 + h * 8;
                    if (rr < cnt) {
                        const int orow = idx[rr];
                        if (col < NCLS)
                            o[(size_t)orow * NCLS + col] = acc[ms][ns][2 * h] + bias[col];
                        if (col + 1 < NCLS)
                            o[(size_t)orow * NCLS + col + 1] = acc[ms][ns][2 * h + 1] + bias[col + 1];
                    }
                }
            }
        }
    }
}

// ---------------- launcher ----------------
extern "C" void kernel_launch(void* const* d_in, const int* in_sizes, int n_in,
                              void* d_out, int out_size) {
    const float* feat = (const float*)d_in[0];
    const void*  mask = d_in[1];
    const float* W1 = (const float*)d_in[2]; const float* b1 = (const float*)d_in[3];
    const float* W2 = (const float*)d_in[4]; const float* b2 = (const float*)d_in[5];
    const float* W3 = (const float*)d_in[6]; const float* b3 = (const float*)d_in[7];

    void *pF, *pW1, *pW2, *pW3, *pH1, *pH2, *pIdx, *pCnt;
    cudaGetSymbolAddress(&pF,  g_featH);
    cudaGetSymbolAddress(&pW1, g_W1t);
    cudaGetSymbolAddress(&pW2, g_W2t);
    cudaGetSymbolAddress(&pW3, g_W3t);
    cudaGetSymbolAddress(&pH1, g_H1);
    cudaGetSymbolAddress(&pH2, g_H2);
    cudaGetSymbolAddress(&pIdx, g_idx);
    cudaGetSymbolAddress(&pCnt, g_cnt);

    constexpr int SMEM = 3 * (64 * 128 + 64 * 128);   // 48 KB
    cudaFuncSetAttribute(gemm_hmma<0>, cudaFuncAttributeMaxDynamicSharedMemorySize, SMEM);
    cudaFuncSetAttribute(gemm_hmma<1>, cudaFuncAttributeMaxDynamicSharedMemorySize, SMEM);

    // output zeros (invalid rows stay 0)
    cudaMemsetAsync(d_out, 0, (size_t)out_size * sizeof(float));
    // valid-row compaction
    build_idx<<<1, 1024>>>(mask, (int*)pIdx, (int*)pCnt);
    // fused prep: gather+convert valid rows AND all 3 weight transposes
    prep<<<MROWS + T1 + T2 + T3, 256>>>(
        feat, (const int*)pIdx, (const int*)pCnt, (__half*)pF,
        W1, W2, W3, (__half*)pW1, (__half*)pW2, (__half*)pW3);
    // MLP on compacted rows (grid.x = N-tiles so concurrent CTAs share A via L2)
    gemm_hmma<0><<<dim3(HID / 64, MROWS / 64), 128, SMEM>>>(
        (const __half*)pF, (const __half*)pW1, b1, pH1,
        (const int*)pIdx, (const int*)pCnt, FLAT);
    gemm_hmma<0><<<dim3(HID / 64, MROWS / 64), 128, SMEM>>>(
        (const __half*)pH1, (const __half*)pW2, b2, pH2,
        (const int*)pIdx, (const int*)pCnt, HID);
    gemm_hmma<1><<<dim3(NPAD / 64, MROWS / 64), 128, SMEM>>>(
        (const __half*)pH2, (const __half*)pW3, b3, d_out,
        (const int*)pIdx, (const int*)pCnt, HID);
    (void)in_sizes; (void)n_in;
}

// round 16
// speedup vs baseline: 1.1438x; 1.1063x over previous
#include <cuda_runtime.h>
#include <cuda_fp16.h>
#include <stdint.h>

// ---------------- problem constants ----------------
static constexpr int MROWS = 8192;          // 16*512
static constexpr int FLAT  = 12544;         // 7*7*256
static constexpr int HID   = 1024;
static constexpr int NCLS  = 81;
static constexpr int NPAD  = 128;

// prep kernel block ranges
static constexpr int T1 = (HID / 32) * (FLAT / 32);   // 12544 W1 tiles
static constexpr int T2 = (HID / 32) * (HID / 32);    // 1024  W2 tiles
static constexpr int T3 = (NPAD / 32) * (HID / 32);   // 128   W3 tiles

// ---------------- scratch (__device__ globals; no allocs allowed) ----------
__device__ __half g_featH[(size_t)MROWS * FLAT];   // compacted fp16 A
__device__ __half g_W1t[(size_t)HID * FLAT];       // [N,K] K-major
__device__ __half g_W2t[(size_t)HID * HID];
__device__ __half g_W3t[(size_t)NPAD * HID];       // rows 81..127 zero
__device__ __half g_H1[(size_t)MROWS * HID];
__device__ __half g_H2[(size_t)MROWS * HID];
__device__ int    g_idx[MROWS];
__device__ int    g_cnt;

// ---------------- helpers ----------------
__device__ __forceinline__ uint32_t smem_u32(const void* p) {
    uint32_t a;
    asm("{ .reg .u64 t; cvta.to.shared.u64 t, %1; cvt.u32.u64 %0, t; }" : "=r"(a) : "l"(p));
    return a;
}
#define SWZ(o) ((o) ^ (((o) >> 3) & 0x70))

__device__ __forceinline__ void cp16(uint32_t dst, const void* src) {
    asm volatile("cp.async.cg.shared.global [%0], [%1], 16;" :: "r"(dst), "l"(src) : "memory");
}
__device__ __forceinline__ void cp_commit() { asm volatile("cp.async.commit_group;" ::: "memory"); }
__device__ __forceinline__ void cp_wait1() { asm volatile("cp.async.wait_group 1;" ::: "memory"); }
__device__ __forceinline__ void cp_wait0() { asm volatile("cp.async.wait_group 0;" ::: "memory"); }

__device__ __forceinline__ void ldsm4(uint32_t (&r)[4], uint32_t addr) {
    asm volatile("ldmatrix.sync.aligned.m8n8.x4.shared.b16 {%0,%1,%2,%3}, [%4];"
        : "=r"(r[0]), "=r"(r[1]), "=r"(r[2]), "=r"(r[3]) : "r"(addr));
}
__device__ __forceinline__ void mma16816(float (&d)[4], const uint32_t (&a)[4],
                                         uint32_t b0, uint32_t b1) {
    asm volatile("mma.sync.aligned.m16n8k16.row.col.f32.f16.f16.f32 "
        "{%0,%1,%2,%3}, {%4,%5,%6,%7}, {%8,%9}, {%0,%1,%2,%3};"
        : "+f"(d[0]), "+f"(d[1]), "+f"(d[2]), "+f"(d[3])
        : "r"(a[0]), "r"(a[1]), "r"(a[2]), "r"(a[3]), "r"(b0), "r"(b1));
}

// ---------------- valid-row compaction (ballot scan, stable) ----------------
__global__ void build_idx(const void* __restrict__ maskp,
                          int* __restrict__ idx, int* __restrict__ cntp) {
    __shared__ int swarp[32];
    __shared__ int s_is8, s_base, s_total;
    const int tid = threadIdx.x, wid = tid >> 5, lane = tid & 31;
    if (tid == 0) {
        const unsigned char* m8 = (const unsigned char*)maskp;
        bool i8 = false;
        for (int i = 1; i < 256; ++i)
            if ((i & 3) && m8[i]) i8 = true;
        s_is8 = i8 ? 1 : 0;
        s_base = 0;
    }
    __syncthreads();
    const int is8 = s_is8;
    for (int chunk = 0; chunk < MROWS; chunk += 1024) {
        const int r = chunk + tid;
        const int v = is8 ? (((const unsigned char*)maskp)[r] != 0)
                          : (((const int*)maskp)[r] != 0);
        const unsigned bal = __ballot_sync(0xFFFFFFFFu, v);
        const int lanePre = __popc(bal & ((1u << lane) - 1u));
        if (lane == 0) swarp[wid] = __popc(bal);
        __syncthreads();
        if (wid == 0) {
            int orig = swarp[lane], x = orig;
            #pragma unroll
            for (int off = 1; off < 32; off <<= 1) {
                int y = __shfl_up_sync(0xFFFFFFFFu, x, off);
                if (lane >= off) x += y;
            }
            swarp[lane] = x - orig;           // exclusive prefix
            if (lane == 31) s_total = x;
        }
        __syncthreads();
        if (v) idx[s_base + swarp[wid] + lanePre] = r;
        __syncthreads();
        if (tid == 0) s_base += s_total;
        __syncthreads();
    }
    if (tid == 0) *cntp = s_base;
}

// ---------------- fused prep: row gather+cvt AND all weight transposes -----
__global__ void __launch_bounds__(256)
prep(const float* __restrict__ feat, const int* __restrict__ idx,
     const int* __restrict__ cntp, __half* __restrict__ fOut,
     const float* __restrict__ W1, const float* __restrict__ W2,
     const float* __restrict__ W3, __half* __restrict__ W1t,
     __half* __restrict__ W2t, __half* __restrict__ W3t) {
    __shared__ float t[32][33];
    int b = blockIdx.x;
    const int tid = threadIdx.x;

    if (b < MROWS) {                              // ---- gather role ----
        if (b >= *cntp) return;
        const float4* in = (const float4*)(feat + (size_t)idx[b] * FLAT);
        uint2* o = (uint2*)(fOut + (size_t)b * FLAT);
        for (int i = tid; i < FLAT / 4; i += 256) {
            float4 v = in[i];
            __half2 a = __floats2half2_rn(v.x, v.y), bb = __floats2half2_rn(v.z, v.w);
            o[i] = make_uint2(*(uint32_t*)&a, *(uint32_t*)&bb);
        }
        return;
    }
    b -= MROWS;                                   // ---- transpose role ----
    const float* W; __half* Wt; int K, N, nx;
    if (b < T1)      { W = W1; Wt = W1t; K = FLAT; N = HID;  nx = HID / 32; }
    else if (b < T1 + T2) { b -= T1; W = W2; Wt = W2t; K = HID; N = HID; nx = HID / 32; }
    else             { b -= T1 + T2; W = W3; Wt = W3t; K = HID; N = NCLS; nx = NPAD / 32; }
    const int n0 = (b % nx) * 32, k0 = (b / nx) * 32;
    const int tx = tid & 31, ty = tid >> 5;
    #pragma unroll
    for (int i = 0; i < 32; i += 8) {
        int n = n0 + tx;
        t[ty + i][tx] = (n < N) ? W[(size_t)(k0 + ty + i) * N + n] : 0.f;
    }
    __syncthreads();
    #pragma unroll
    for (int i = 0; i < 32; i += 8)
        Wt[(size_t)(n0 + ty + i) * K + k0 + tx] = __float2half_rn(t[tx][ty + i]);
}

// ---------------- HMMA GEMM: C = post(A[Mc,K] @ Wt[N,K]^T + bias) ----------
// BM=64, BN=64, BK=64. 128 thr = 4 warps (2Mx2N), warp tile 32x32, acc=32.
// 3-stage cp.async (48 KB) -> 4 CTAs/SM. K compile-time; all gmem pointers and
// swizzled smem offsets hoisted out of the K-loop (pointer-bump addressing).
// Compacted rows; CTAs beyond padded count early-exit.
// MODE 0: relu, fp16 out (stride HID).  MODE 1: scatter via idx, fp32 out (stride NCLS).
template <int MODE, int K>
__global__ void __launch_bounds__(128, 4)
gemm_hmma(const __half* __restrict__ A, const __half* __restrict__ Wt,
          const float* __restrict__ bias, void* __restrict__ outp,
          const int* __restrict__ idx, const int* __restrict__ cntp) {
    constexpr int A_BYTES = 64 * 128;
    constexpr int B_BYTES = 64 * 128;
    constexpr int STAGE   = A_BYTES + B_BYTES;   // 16 KB
    constexpr int KC      = K >> 6;

    const int cnt = *cntp;
    const int m0 = blockIdx.y * 64;
    if (m0 >= ((cnt + 63) & ~63)) return;

    extern __shared__ char smem[];
    const uint32_t tiles = smem_u32(smem);

    const int tid = threadIdx.x, wid = tid >> 5, lid = tid & 31;
    const int n0 = blockIdx.x * 64;
    const int wm = (wid >> 1) * 32, wn = (wid & 1) * 32;

    float acc[2][4][4];
    #pragma unroll
    for (int a = 0; a < 2; ++a)
        #pragma unroll
        for (int b = 0; b < 4; ++b)
            #pragma unroll
            for (int c = 0; c < 4; ++c) acc[a][b][c] = 0.f;

    // ---- hoisted cp.async addressing: rows r0+16i, constant seg ----
    const int r0 = tid >> 3, seg = tid & 7;
    const __half* pA = A + (size_t)(m0 + r0) * K + seg * 8;
    const __half* pB = Wt + (size_t)(n0 + r0) * K + seg * 8;
    uint32_t cpOff[4];
    #pragma unroll
    for (int i = 0; i < 4; ++i)
        cpOff[i] = SWZ((uint32_t)((r0 + 16 * i) * 128 + seg * 16));

    auto load_stage = [&](int c) {
        const uint32_t sA = tiles + (uint32_t)(c % 3) * STAGE, sB = sA + A_BYTES;
        const __half* Ab = pA + c * 64;
        const __half* Bb = pB + c * 64;
        #pragma unroll
        for (int i = 0; i < 4; ++i)
            cp16(sA + cpOff[i], Ab + (size_t)i * 16 * K);
        #pragma unroll
        for (int i = 0; i < 4; ++i)
            cp16(sB + cpOff[i], Bb + (size_t)i * 16 * K);
        cp_commit();
    };

    // ---- hoisted ldsm fragment offsets (swizzled, loop-invariant) ----
    const int lrow = lid & 15, lkh = lid >> 4;
    uint32_t offA[2][4], offB[2][4];
    #pragma unroll
    for (int k0i = 0; k0i < 4; ++k0i) {
        #pragma unroll
        for (int ms = 0; ms < 2; ++ms)
            offA[ms][k0i] = SWZ((uint32_t)((wm + ms * 16 + lrow) * 128 +
                                           (k0i * 16 + lkh * 8) * 2));
        #pragma unroll
        for (int nn = 0; nn < 2; ++nn)
            offB[nn][k0i] = SWZ((uint32_t)((wn + nn * 16 + lrow) * 128 +
                                           (k0i * 16 + lkh * 8) * 2));
    }

    load_stage(0);
    load_stage(1);

    for (int c = 0; c < KC; ++c) {
        if (c >= KC - 1) cp_wait0(); else cp_wait1();
        __syncthreads();
        if (c + 2 < KC) load_stage(c + 2);
        const uint32_t sA = tiles + (uint32_t)(c % 3) * STAGE, sB = sA + A_BYTES;
        #pragma unroll
        for (int k0i = 0; k0i < 4; ++k0i) {
            uint32_t bfr[2][4];
            #pragma unroll
            for (int nn = 0; nn < 2; ++nn)
                ldsm4(bfr[nn], sB + offB[nn][k0i]);
            #pragma unroll
            for (int ms = 0; ms < 2; ++ms) {
                uint32_t afr[4];
                ldsm4(afr, sA + offA[ms][k0i]);
                #pragma unroll
                for (int ns = 0; ns < 4; ++ns)
                    mma16816(acc[ms][ns], afr, bfr[ns >> 1][ns & 1], bfr[ns >> 1][(ns & 1) + 2]);
            }
        }
    }

    #pragma unroll
    for (int ms = 0; ms < 2; ++ms) {
        const int r = m0 + wm + ms * 16 + (lid >> 2);
        #pragma unroll
        for (int ns = 0; ns < 4; ++ns) {
            const int col = n0 + wn + ns * 8 + 2 * (lid & 3);
            if (MODE == 0) {
                float bx = bias[col], by = bias[col + 1];
                __half* o = (__half*)outp;
                *(__half2*)(o + (size_t)r * HID + col) =
                    __floats2half2_rn(fmaxf(acc[ms][ns][0] + bx, 0.f),
                                      fmaxf(acc[ms][ns][1] + by, 0.f));
                *(__half2*)(o + (size_t)(r + 8) * HID + col) =
                    __floats2half2_rn(fmaxf(acc[ms][ns][2] + bx, 0.f),
                                      fmaxf(acc[ms][ns][3] + by, 0.f));
            } else {
                float* o = (float*)outp;
                #pragma unroll
                for (int h = 0; h < 2; ++h) {
                    const int rr = r + h * 8;
                    if (rr < cnt) {
                        const int orow = idx[rr];
                        if (col < NCLS)
                            o[(size_t)orow * NCLS + col] = acc[ms][ns][2 * h] + bias[col];
                        if (col + 1 < NCLS)
                            o[(size_t)orow * NCLS + col + 1] = acc[ms][ns][2 * h + 1] + bias[col + 1];
                    }
                }
            }
        }
    }
}

// ---------------- launcher ----------------
extern "C" void kernel_launch(void* const* d_in, const int* in_sizes, int n_in,
                              void* d_out, int out_size) {
    const float* feat = (const float*)d_in[0];
    const void*  mask = d_in[1];
    const float* W1 = (const float*)d_in[2]; const float* b1 = (const float*)d_in[3];
    const float* W2 = (const float*)d_in[4]; const float* b2 = (const float*)d_in[5];
    const float* W3 = (const float*)d_in[6]; const float* b3 = (const float*)d_in[7];

    void *pF, *pW1, *pW2, *pW3, *pH1, *pH2, *pIdx, *pCnt;
    cudaGetSymbolAddress(&pF,  g_featH);
    cudaGetSymbolAddress(&pW1, g_W1t);
    cudaGetSymbolAddress(&pW2, g_W2t);
    cudaGetSymbolAddress(&pW3, g_W3t);
    cudaGetSymbolAddress(&pH1, g_H1);
    cudaGetSymbolAddress(&pH2, g_H2);
    cudaGetSymbolAddress(&pIdx, g_idx);
    cudaGetSymbolAddress(&pCnt, g_cnt);

    constexpr int SMEM = 3 * (64 * 128 + 64 * 128);   // 48 KB
    cudaFuncSetAttribute(gemm_hmma<0, FLAT>, cudaFuncAttributeMaxDynamicSharedMemorySize, SMEM);
    cudaFuncSetAttribute(gemm_hmma<0, HID>,  cudaFuncAttributeMaxDynamicSharedMemorySize, SMEM);
    cudaFuncSetAttribute(gemm_hmma<1, HID>,  cudaFuncAttributeMaxDynamicSharedMemorySize, SMEM);

    // output zeros (invalid rows stay 0)
    cudaMemsetAsync(d_out, 0, (size_t)out_size * sizeof(float));
    // valid-row compaction
    build_idx<<<1, 1024>>>(mask, (int*)pIdx, (int*)pCnt);
    // fused prep: gather+convert valid rows AND all 3 weight transposes
    prep<<<MROWS + T1 + T2 + T3, 256>>>(
        feat, (const int*)pIdx, (const int*)pCnt, (__half*)pF,
        W1, W2, W3, (__half*)pW1, (__half*)pW2, (__half*)pW3);
    // MLP on compacted rows (grid.x = N-tiles so concurrent CTAs share A via L2)
    gemm_hmma<0, FLAT><<<dim3(HID / 64, MROWS / 64), 128, SMEM>>>(
        (const __half*)pF, (const __half*)pW1, b1, pH1,
        (const int*)pIdx, (const int*)pCnt);
    gemm_hmma<0, HID><<<dim3(HID / 64, MROWS / 64), 128, SMEM>>>(
        (const __half*)pH1, (const __half*)pW2, b2, pH2,
        (const int*)pIdx, (const int*)pCnt);
    gemm_hmma<1, HID><<<dim3(NPAD / 64, MROWS / 64), 128, SMEM>>>(
        (const __half*)pH2, (const __half*)pW3, b3, d_out,
        (const int*)pIdx, (const int*)pCnt);
    (void)in_sizes; (void)n_in;
}